// round 5
// baseline (speedup 1.0000x reference)
#include <cuda_runtime.h>
#include <cstdint>
#include <math.h>

#define T_ 512
#define B_ 64
#define N_ 1024
#define G_ 4096   // 4*N
#define SP 132    // smem pitch (u32) for h tiles

// ---------------- static device scratch ----------------
__device__ float g_Pf[(size_t)T_ * B_ * G_];
__device__ float g_Pb[(size_t)T_ * B_ * G_];
__device__ float g_Pc[(size_t)T_ * B_ * G_];
__device__ float g_bi[(size_t)T_ * B_ * 2 * N_];
__device__ float g_h[6][B_ * N_];
__device__ float g_c[3][B_ * N_];
__device__ uint32_t g_WihT[16 * 1024 * 1024];          // tf32 W_ih: f(4M) b(4M) c(8M)
__device__ uint32_t g_Wsw_bi[2 * 64 * 64 * 1024];      // swizzled tf32 W_hh fwd/bwd
__device__ uint32_t g_Wsw_c[128 * 32 * 1024];          // swizzled tf32 W_hh cell

__device__ unsigned g_barc[2] = {0, 0};
__device__ unsigned g_barg[2] = {0, 0};

__device__ __forceinline__ void grid_barrier(int which, unsigned nb) {
    __syncthreads();
    if (threadIdx.x == 0) {
        __threadfence();
        volatile unsigned* gen = &g_barg[which];
        unsigned g = *gen;
        if (atomicAdd(&g_barc[which], 1) == nb - 1) {
            g_barc[which] = 0;
            __threadfence();
            atomicExch((unsigned*)gen, g + 1);
        } else {
            while (*gen == g) { __nanosleep(64); }
            __threadfence();
        }
    }
    __syncthreads();
}

__global__ void zero_state_kernel() {
    int i = blockIdx.x * blockDim.x + threadIdx.x;
    if (i < 6 * B_ * N_) ((float*)g_h)[i] = 0.0f;
    if (i < 3 * B_ * N_) ((float*)g_c)[i] = 0.0f;
}

// ---------------- tf32 / mma / cp.async helpers ----------------
__device__ __forceinline__ uint32_t f2tf32(float x) {
    uint32_t r;
    asm("cvt.rna.tf32.f32 %0, %1;" : "=r"(r) : "f"(x));
    return r;
}
__device__ __forceinline__ void mma_tf32(float* c, const uint32_t* a, const uint32_t* b) {
    asm volatile(
        "mma.sync.aligned.m16n8k8.row.col.f32.tf32.tf32.f32 "
        "{%0,%1,%2,%3}, {%4,%5,%6,%7}, {%8,%9}, {%0,%1,%2,%3};"
        : "+f"(c[0]), "+f"(c[1]), "+f"(c[2]), "+f"(c[3])
        : "r"(a[0]), "r"(a[1]), "r"(a[2]), "r"(a[3]), "r"(b[0]), "r"(b[1]));
}
__device__ __forceinline__ void cp16(uint32_t dst, const void* src) {
    asm volatile("cp.async.cg.shared.global [%0], [%1], 16;" :: "r"(dst), "l"(src));
}
__device__ __forceinline__ void cp_commit() { asm volatile("cp.async.commit_group;"); }
template <int NN> __device__ __forceinline__ void cp_wait() {
    asm volatile("cp.async.wait_group %0;" :: "n"(NN));
}

// ---------------- one-time W_ih conversion ----------------
__global__ void wconv_ih_kernel(const float* __restrict__ Wf,
                                const float* __restrict__ Wb,
                                const float* __restrict__ Wc) {
    size_t i = (size_t)blockIdx.x * blockDim.x + threadIdx.x;
    const float* src;
    size_t off;
    if (i < (1u << 20))      { src = Wf; off = i; }
    else if (i < (2u << 20)) { src = Wb; off = i - (1u << 20); }
    else                     { src = Wc; off = i - (2u << 20); }
    float4 v = ((const float4*)src)[off];
    uint4 u;
    u.x = f2tf32(v.x); u.y = f2tf32(v.y); u.z = f2tf32(v.z); u.w = f2tf32(v.w);
    ((uint4*)g_WihT)[i] = u;
}

// ---------------- one-time W_hh fragment swizzles ----------------
// bilstm: idx = region*65536 + k16*1024 + nw*256 + nf*128 + lane*4 + kp*2 + r
__global__ void wswz_bi_kernel(const float* __restrict__ Wf,
                               const float* __restrict__ Wb) {
    size_t idx = (size_t)blockIdx.x * blockDim.x + threadIdx.x;
    unsigned region = idx >> 16;
    unsigned w = idx & 65535;
    int dir = region >> 6, ublk = region & 63;
    int r = w & 1, kp = (w >> 1) & 1, lane = (w >> 2) & 31;
    int nf = (w >> 7) & 1, nw = (w >> 8) & 3, k16 = (w >> 10) & 63;
    int gid = lane >> 2, tig = lane & 3;
    int col = nw * 16 + nf * 8 + gid;
    int gate = col >> 4, u = col & 15;
    int row = gate * N_ + ublk * 16 + u;
    int k = k16 * 16 + kp * 8 + r * 4 + tig;
    const float* W = dir ? Wb : Wf;
    g_Wsw_bi[idx] = f2tf32(W[(size_t)row * N_ + k]);
}
// cell: idx = blk*32768 + k16*512 + nw*128 + lane*4 + kp*2 + r
__global__ void wswz_cell_kernel(const float* __restrict__ Wc) {
    size_t idx = (size_t)blockIdx.x * blockDim.x + threadIdx.x;
    unsigned blk = idx >> 15;
    unsigned w = idx & 32767;
    int r = w & 1, kp = (w >> 1) & 1, lane = (w >> 2) & 31;
    int nw = (w >> 7) & 3, k16 = (w >> 9) & 63;
    int gid = lane >> 2, tig = lane & 3;
    int col = nw * 8 + gid;
    int gate = col >> 3, u = col & 7;
    int row = gate * N_ + blk * 8 + u;
    int k = k16 * 16 + kp * 8 + r * 4 + tig;
    g_Wsw_c[idx] = f2tf32(Wc[(size_t)row * N_ + k]);
}

// ---------------- tf32 GEMM: 128x128x16, cp.async double buffered ----------------
__global__ __launch_bounds__(256, 2) void gemm_tf32_kernel(
    const float* __restrict__ Aext,
    const uint32_t* __restrict__ Wt,
    const float* __restrict__ bias,
    int K, int a_mode, int dst_sel)
{
    float* C = (dst_sel == 0) ? g_Pf : (dst_sel == 1) ? g_Pb : g_Pc;
    const float* A = (a_mode == 2) ? (const float*)g_bi : Aext;

    __shared__ __align__(16) float As[2][128 * 20];
    __shared__ __align__(16) uint32_t Ws[2][128 * 20];

    const int tid = threadIdx.x;
    const int m0 = blockIdx.y * 128;
    const int g0 = blockIdx.x * 128;

    const int lr = tid >> 2;
    const int lq = tid & 3;
    const float* asrc[2];
    const uint32_t* wsrc[2];
#pragma unroll
    for (int i = 0; i < 2; i++) {
        int m = m0 + lr + 64 * i;
        int prow = (a_mode == 1) ? ((m & 63) * T_ + (m >> 6)) : m;
        asrc[i] = A + (size_t)prow * K + lq * 4;
        wsrc[i] = Wt + (size_t)(g0 + lr + 64 * i) * K + lq * 4;
    }
    uint32_t asm_base[2][2], wsm_base[2][2];
#pragma unroll
    for (int bufi = 0; bufi < 2; bufi++)
#pragma unroll
        for (int i = 0; i < 2; i++) {
            asm_base[bufi][i] = (uint32_t)__cvta_generic_to_shared(&As[bufi][(lr + 64 * i) * 20 + lq * 4]);
            wsm_base[bufi][i] = (uint32_t)__cvta_generic_to_shared(&Ws[bufi][(lr + 64 * i) * 20 + lq * 4]);
        }

    const int lane = tid & 31;
    const int wid = tid >> 5;
    const int gid = lane >> 2;
    const int tig = lane & 3;
    const int wm = (wid & 3) * 32;
    const int wn = (wid >> 2) * 64;

    float acc[2][8][4];
#pragma unroll
    for (int mf = 0; mf < 2; mf++)
#pragma unroll
        for (int nf = 0; nf < 8; nf++)
#pragma unroll
            for (int j = 0; j < 4; j++) acc[mf][nf][j] = 0.0f;

    const int NC = K / 16;
#pragma unroll
    for (int i = 0; i < 2; i++) {
        cp16(asm_base[0][i], asrc[i]);
        cp16(wsm_base[0][i], wsrc[i]);
    }
    cp_commit();

    for (int ch = 0; ch < NC; ch++) {
        const int buf = ch & 1;
        if (ch + 1 < NC) {
            const int nb = (ch + 1) & 1;
            const int k0 = (ch + 1) * 16;
#pragma unroll
            for (int i = 0; i < 2; i++) {
                cp16(asm_base[nb][i], asrc[i] + k0);
                cp16(wsm_base[nb][i], wsrc[i] + k0);
            }
            cp_commit();
            cp_wait<1>();
        } else {
            cp_wait<0>();
        }
        __syncthreads();

        const float* Af = As[buf];
        const uint32_t* Wf = Ws[buf];
#pragma unroll
        for (int ks = 0; ks < 2; ks++) {
            const int kb = ks * 8;
            uint32_t af[2][4];
#pragma unroll
            for (int mf = 0; mf < 2; mf++) {
                int mb = wm + mf * 16;
                af[mf][0] = f2tf32(Af[(mb + gid) * 20 + kb + tig]);
                af[mf][1] = f2tf32(Af[(mb + gid + 8) * 20 + kb + tig]);
                af[mf][2] = f2tf32(Af[(mb + gid) * 20 + kb + tig + 4]);
                af[mf][3] = f2tf32(Af[(mb + gid + 8) * 20 + kb + tig + 4]);
            }
            uint32_t bf[8][2];
#pragma unroll
            for (int nf = 0; nf < 8; nf++) {
                int nb2 = wn + nf * 8 + gid;
                bf[nf][0] = Wf[nb2 * 20 + kb + tig];
                bf[nf][1] = Wf[nb2 * 20 + kb + tig + 4];
            }
#pragma unroll
            for (int mf = 0; mf < 2; mf++)
#pragma unroll
                for (int nf = 0; nf < 8; nf++)
                    mma_tf32(acc[mf][nf], af[mf], bf[nf]);
        }
        __syncthreads();
    }

#pragma unroll
    for (int mf = 0; mf < 2; mf++) {
#pragma unroll
        for (int nf = 0; nf < 8; nf++) {
            int row = m0 + wm + mf * 16 + gid;
            int col = g0 + wn + nf * 8 + 2 * tig;
            float b0 = bias[col], b1 = bias[col + 1];
            float2 v0 = make_float2(acc[mf][nf][0] + b0, acc[mf][nf][1] + b1);
            float2 v1 = make_float2(acc[mf][nf][2] + b0, acc[mf][nf][3] + b1);
            *(float2*)&C[(size_t)row * G_ + col] = v0;
            *(float2*)&C[(size_t)(row + 8) * G_ + col] = v1;
        }
    }
}

// ---------------- persistent bilstm recurrence ----------------
// 128 blocks x 512 threads (16 warps). Warp: wm=(wid&1)*32, n-warp jn=wid>>1 (8 cols wide).
// h staged via cp.async double-buffer (raw tf32-bit floats); W fragments from gmem,
// whole-chunk register queue (8 uint4 preloaded one chunk ahead).
__global__ __launch_bounds__(512, 1) void bilstm_mma_kernel()
{
    extern __shared__ float smem_f[];
    float* hs[2] = { smem_f, smem_f + 64 * SP };
    float* gates = smem_f + 2 * 64 * SP;      // [64][68]

    const int bid = blockIdx.x;
    const int dir = bid >> 6;
    const int u0 = (bid & 63) * 16;
    const float* Pbase = dir ? g_Pb : g_Pf;
    float* c = g_c[dir];

    const int tid = threadIdx.x;
    const int lane = tid & 31;
    const int wid = tid >> 5;
    const int gid = lane >> 2;
    const int tig = lane & 3;
    const int wm = (wid & 1) * 32;
    const int jn = wid >> 1;
    const int wn = jn * 8;

    const uint32_t* wp = g_Wsw_bi + ((size_t)(dir * 64 + (bid & 63)) << 16)
                       + ((jn >> 1) * 256 + (jn & 1) * 128 + lane * 4);

    // staging geometry: 4 uint4 per thread per chunk
    const int srow = tid >> 5;        // base rows srow, srow+16, +32, +48 via j*16? no:
    // i = tid + 512*j -> row = i>>5 = srow + 16*j, q = lane
    uint32_t hs_addr[2];
    hs_addr[0] = (uint32_t)__cvta_generic_to_shared(hs[0]) + (srow * SP + lane * 4) * 4;
    hs_addr[1] = (uint32_t)__cvta_generic_to_shared(hs[1]) + (srow * SP + lane * 4) * 4;

    for (int s = 0; s < T_; s++) {
        const int t = dir ? (T_ - 1 - s) : s;
        const float* P = Pbase + (size_t)t * B_ * G_;
        const float* h_prev = g_h[2 * dir + (s & 1)];
        float* h_next = g_h[2 * dir + ((s + 1) & 1)];
        float* hist = g_bi + (size_t)t * B_ * 2 * N_ + dir * N_;

        // preload chunk 0 (h) + chunk 0 W queue
#pragma unroll
        for (int j = 0; j < 4; j++)
            cp16(hs_addr[0] + j * 16 * SP * 4,
                 h_prev + (size_t)(srow + 16 * j) * N_ + lane * 4);
        cp_commit();

        uint4 wcur[8], wnext[8];
#pragma unroll
        for (int l = 0; l < 8; l++)
            wcur[l] = *(const uint4*)(wp + (size_t)l * 1024);

        float acc[2][4];
#pragma unroll
        for (int mf = 0; mf < 2; mf++)
#pragma unroll
            for (int j = 0; j < 4; j++) acc[mf][j] = 0.0f;

        for (int ch = 0; ch < 8; ch++) {
            const int buf = ch & 1;
            if (ch + 1 < 8) {
#pragma unroll
                for (int j = 0; j < 4; j++)
                    cp16(hs_addr[buf ^ 1] + j * 16 * SP * 4,
                         h_prev + (size_t)(srow + 16 * j) * N_ + (ch + 1) * 128 + lane * 4);
                cp_commit();
                cp_wait<1>();
            } else {
                cp_wait<0>();
            }
            __syncthreads();

            if (ch + 1 < 8) {
#pragma unroll
                for (int l = 0; l < 8; l++)
                    wnext[l] = *(const uint4*)(wp + (size_t)((ch + 1) * 8 + l) * 1024);
            }

            const uint32_t* Hu = (const uint32_t*)hs[buf];
#pragma unroll
            for (int l = 0; l < 8; l++) {
#pragma unroll
                for (int kp = 0; kp < 2; kp++) {
                    const int kb = l * 16 + kp * 8;
                    uint32_t af[2][4];
#pragma unroll
                    for (int mf = 0; mf < 2; mf++) {
                        int mb = wm + mf * 16;
                        af[mf][0] = Hu[(mb + gid) * SP + kb + tig];
                        af[mf][1] = Hu[(mb + gid + 8) * SP + kb + tig];
                        af[mf][2] = Hu[(mb + gid) * SP + kb + tig + 4];
                        af[mf][3] = Hu[(mb + gid + 8) * SP + kb + tig + 4];
                    }
                    uint32_t bf[2];
                    if (kp == 0) { bf[0] = wcur[l].x; bf[1] = wcur[l].y; }
                    else         { bf[0] = wcur[l].z; bf[1] = wcur[l].w; }
#pragma unroll
                    for (int mf = 0; mf < 2; mf++)
                        mma_tf32(acc[mf], af[mf], bf);
                }
            }
            if (ch + 1 < 8) {
#pragma unroll
                for (int l = 0; l < 8; l++) wcur[l] = wnext[l];
            }
            __syncthreads();
        }

        // write gate sums
#pragma unroll
        for (int mf = 0; mf < 2; mf++) {
            int row = wm + mf * 16 + gid;
            int col = wn + 2 * tig;
            gates[row * 68 + col]           = acc[mf][0];
            gates[row * 68 + col + 1]       = acc[mf][1];
            gates[(row + 8) * 68 + col]     = acc[mf][2];
            gates[(row + 8) * 68 + col + 1] = acc[mf][3];
        }
        __syncthreads();

        // activation: 64 b x 16 u = 1024 pairs -> 2 per thread
#pragma unroll
        for (int i = 0; i < 2; i++) {
            int p = tid + 512 * i;
            int bl = p >> 4;
            int u = p & 15;
            int ug = u0 + u;
            const float* Pb = P + (size_t)bl * G_;
            float ig = gates[bl * 68 + u]      + Pb[ug];
            float fg = gates[bl * 68 + 16 + u] + Pb[N_ + ug];
            float gg = gates[bl * 68 + 32 + u] + Pb[2 * N_ + ug];
            float og = gates[bl * 68 + 48 + u] + Pb[3 * N_ + ug];
            ig = 1.0f / (1.0f + expf(-ig));
            fg = 1.0f / (1.0f + expf(-fg));
            gg = tanhf(gg);
            og = 1.0f / (1.0f + expf(-og));
            size_t ci = (size_t)bl * N_ + ug;
            float cn = fg * c[ci] + ig * gg;
            c[ci] = cn;
            float hn_t = __uint_as_float(f2tf32(og * tanhf(cn)));
            h_next[ci] = hn_t;
            hist[(size_t)bl * 2 * N_ + ug] = hn_t;
        }
        grid_barrier(0, 128);
    }
}

// ---------------- persistent cell recurrence ----------------
// 128 blocks x 512 threads (16 warps). k-split: kh=wid>>3 (k halves of 512).
// Within half: wm=(w8&1)*32, wn=(w8>>1)*8 over n32. Partial gates summed in smem.
__global__ __launch_bounds__(512, 1) void cell_mma_kernel(float* __restrict__ out)
{
    extern __shared__ float smem_f[];
    // hs[buf][half]: 4 tiles of 64*SP
    float* hsb[2][2] = {
        { smem_f,               smem_f + 64 * SP },
        { smem_f + 2 * 64 * SP, smem_f + 3 * 64 * SP }
    };
    float* gates0 = smem_f + 4 * 64 * SP;          // [64][36]
    float* gates1 = gates0 + 64 * 36;

    const int bid = blockIdx.x;
    const int u0 = bid * 8;
    float* c = g_c[2];

    const int tid = threadIdx.x;
    const int lane = tid & 31;
    const int wid = tid >> 5;
    const int gid = lane >> 2;
    const int tig = lane & 3;
    const int kh = wid >> 3;
    const int w8 = wid & 7;
    const int wm = (w8 & 1) * 32;
    const int nwq = w8 >> 1;
    const int wn = nwq * 8;

    const uint32_t* wp = g_Wsw_c + ((size_t)bid << 15) + nwq * 128 + lane * 4;
    const int k16base = kh * 32;

    // staging: 8 uint4/thread/iter: i = tid + 512*j -> half=(i>>11), w=i&2047, row=w>>5, q=lane
    const int srow = tid >> 5;  // rows srow+16*jj within each half, jj = j&3; half = j>>2
    uint32_t hs_addr[2][2];
#pragma unroll
    for (int b = 0; b < 2; b++)
#pragma unroll
        for (int hh = 0; hh < 2; hh++)
            hs_addr[b][hh] = (uint32_t)__cvta_generic_to_shared(hsb[b][hh]) + (srow * SP + lane * 4) * 4;

    for (int s = 0; s < T_; s++) {
        const float* P = g_Pc + (size_t)s * B_ * G_;
        const float* h_prev = g_h[4 + (s & 1)];
        float* h_next = g_h[4 + ((s + 1) & 1)];

        // preload iter 0 (both halves)
#pragma unroll
        for (int hh = 0; hh < 2; hh++)
#pragma unroll
            for (int j = 0; j < 4; j++)
                cp16(hs_addr[0][hh] + j * 16 * SP * 4,
                     h_prev + (size_t)(srow + 16 * j) * N_ + hh * 512 + lane * 4);
        cp_commit();

        uint4 wcur[8], wnext[8];
#pragma unroll
        for (int l = 0; l < 8; l++)
            wcur[l] = *(const uint4*)(wp + (size_t)(k16base + l) * 512);

        float acc[2][4];
#pragma unroll
        for (int mf = 0; mf < 2; mf++)
#pragma unroll
            for (int j = 0; j < 4; j++) acc[mf][j] = 0.0f;

        for (int ch = 0; ch < 4; ch++) {
            const int buf = ch & 1;
            if (ch + 1 < 4) {
#pragma unroll
                for (int hh = 0; hh < 2; hh++)
#pragma unroll
                    for (int j = 0; j < 4; j++)
                        cp16(hs_addr[buf ^ 1][hh] + j * 16 * SP * 4,
                             h_prev + (size_t)(srow + 16 * j) * N_ + hh * 512 + (ch + 1) * 128 + lane * 4);
                cp_commit();
                cp_wait<1>();
            } else {
                cp_wait<0>();
            }
            __syncthreads();

            if (ch + 1 < 4) {
#pragma unroll
                for (int l = 0; l < 8; l++)
                    wnext[l] = *(const uint4*)(wp + (size_t)(k16base + (ch + 1) * 8 + l) * 512);
            }

            const uint32_t* Hu = (const uint32_t*)hsb[buf][kh];
#pragma unroll
            for (int l = 0; l < 8; l++) {
#pragma unroll
                for (int kp = 0; kp < 2; kp++) {
                    const int kb = l * 16 + kp * 8;
                    uint32_t af[2][4];
#pragma unroll
                    for (int mf = 0; mf < 2; mf++) {
                        int mb = wm + mf * 16;
                        af[mf][0] = Hu[(mb + gid) * SP + kb + tig];
                        af[mf][1] = Hu[(mb + gid + 8) * SP + kb + tig];
                        af[mf][2] = Hu[(mb + gid) * SP + kb + tig + 4];
                        af[mf][3] = Hu[(mb + gid + 8) * SP + kb + tig + 4];
                    }
                    uint32_t bf[2];
                    if (kp == 0) { bf[0] = wcur[l].x; bf[1] = wcur[l].y; }
                    else         { bf[0] = wcur[l].z; bf[1] = wcur[l].w; }
#pragma unroll
                    for (int mf = 0; mf < 2; mf++)
                        mma_tf32(acc[mf], af[mf], bf);
                }
            }
            if (ch + 1 < 4) {
#pragma unroll
                for (int l = 0; l < 8; l++) wcur[l] = wnext[l];
            }
            __syncthreads();
        }

        float* G = kh ? gates1 : gates0;
#pragma unroll
        for (int mf = 0; mf < 2; mf++) {
            int row = wm + mf * 16 + gid;
            int col = wn + 2 * tig;
            G[row * 36 + col]           = acc[mf][0];
            G[row * 36 + col + 1]       = acc[mf][1];
            G[(row + 8) * 36 + col]     = acc[mf][2];
            G[(row + 8) * 36 + col + 1] = acc[mf][3];
        }
        __syncthreads();

        // activation: 64 b x 8 u = 512 pairs -> 1 per thread
        {
            int bl = tid >> 3;
            int u = tid & 7;
            int ug = u0 + u;
            const float* Pb = P + (size_t)bl * G_;
            float ig = gates0[bl * 36 + u]      + gates1[bl * 36 + u]      + Pb[ug];
            float fg = gates0[bl * 36 + 8 + u]  + gates1[bl * 36 + 8 + u]  + Pb[N_ + ug];
            float gg = gates0[bl * 36 + 16 + u] + gates1[bl * 36 + 16 + u] + Pb[2 * N_ + ug];
            float og = gates0[bl * 36 + 24 + u] + gates1[bl * 36 + 24 + u] + Pb[3 * N_ + ug];
            ig = 1.0f / (1.0f + expf(-ig));
            fg = 1.0f / (1.0f + expf(-fg));
            gg = tanhf(gg);
            og = 1.0f / (1.0f + expf(-og));
            size_t ci = (size_t)bl * N_ + ug;
            float cn = fg * c[ci] + ig * gg;
            c[ci] = cn;
            float hn = og * tanhf(cn);
            out[((size_t)bl * T_ + s) * N_ + ug] = hn;
            h_next[ci] = __uint_as_float(f2tf32(hn));
            if (s == T_ - 1) {
                // (hT, cT) tail in full precision
                const size_t tail = (size_t)B_ * T_ * N_;
                out[tail + ci] = hn;
                out[tail + (size_t)B_ * N_ + ci] = cn;
            }
        }
        grid_barrier(1, 128);
    }
}

// ---------------- host launcher ----------------
extern "C" void kernel_launch(void* const* d_in, const int* in_sizes, int n_in,
                              void* d_out, int out_size) {
    (void)in_sizes; (void)n_in; (void)out_size;
    const float* x     = (const float*)d_in[0];
    const float* Wf_ih = (const float*)d_in[1];
    const float* Wf_hh = (const float*)d_in[2];
    const float* bf    = (const float*)d_in[3];
    const float* Wb_ih = (const float*)d_in[4];
    const float* Wb_hh = (const float*)d_in[5];
    const float* bb    = (const float*)d_in[6];
    const float* Wc_ih = (const float*)d_in[7];
    const float* Wc_hh = (const float*)d_in[8];
    const float* bc    = (const float*)d_in[9];
    float* out = (float*)d_out;

    uint32_t* wih;
    cudaGetSymbolAddress((void**)&wih, g_WihT);
    const uint32_t* wih_f = wih;
    const uint32_t* wih_b = wih + (4u << 20);
    const uint32_t* wih_c = wih + (8u << 20);

    const int bilstm_smem = 2 * 64 * SP * 4 + 64 * 68 * 4;          // 84992
    const int cell_smem   = 4 * 64 * SP * 4 + 2 * 64 * 36 * 4;      // 153600
    cudaFuncSetAttribute(bilstm_mma_kernel, cudaFuncAttributeMaxDynamicSharedMemorySize, bilstm_smem);
    cudaFuncSetAttribute(cell_mma_kernel, cudaFuncAttributeMaxDynamicSharedMemorySize, cell_smem);

    // 1) init + one-time weight prep
    zero_state_kernel<<<(6 * B_ * N_ + 511) / 512, 512>>>();
    wconv_ih_kernel<<<(4 << 20) / 256, 256>>>(Wf_ih, Wb_ih, Wc_ih);
    wswz_bi_kernel<<<(8 << 20) / 256, 256>>>(Wf_hh, Wb_hh);
    wswz_cell_kernel<<<(4 << 20) / 256, 256>>>(Wc_hh);

    // 2) input projections
    dim3 ggrid(G_ / 128, (T_ * B_) / 128);
    gemm_tf32_kernel<<<ggrid, 256>>>(x, wih_f, bf, N_, 1, 0);
    gemm_tf32_kernel<<<ggrid, 256>>>(x, wih_b, bb, N_, 1, 1);

    // 3) bilstm recurrence
    bilstm_mma_kernel<<<128, 512, bilstm_smem>>>();

    // 4) cell input projection (K = 2N)
    gemm_tf32_kernel<<<ggrid, 256>>>(nullptr, wih_c, bc, 2 * N_, 2, 2);

    // 5) cell recurrence + output (+ hT/cT tail at final step)
    cell_mma_kernel<<<128, 512, cell_smem>>>(out);
}

// round 6
// speedup vs baseline: 1.6695x; 1.6695x over previous
#include <cuda_runtime.h>
#include <cuda_fp16.h>
#include <cstdint>
#include <math.h>

#define T_ 512
#define B_ 64
#define N_ 1024
#define G_ 4096   // 4*N
#define SPH 68    // smem pitch (u32) for fp16 h tiles (128 fp16 = 64 u32 + 4 pad)

// ---------------- static device scratch ----------------
__device__ float g_Pf[(size_t)T_ * B_ * G_];
__device__ float g_Pb[(size_t)T_ * B_ * G_];
__device__ float g_Pc[(size_t)T_ * B_ * G_];
__device__ __half g_bi16[(size_t)T_ * B_ * 2 * N_];   // bilstm output, fp16
__device__ __half g_x16[(size_t)B_ * T_ * N_];        // inputs converted to fp16
__device__ __half g_Wih16[16 * 1024 * 1024];          // fp16 W_ih: f(4M) b(4M) c(8M)
__device__ __half g_h16[6][B_ * N_];                  // fp16 recurrent h
__device__ float  g_c[3][B_ * N_];                    // fp32 cell state
__device__ uint32_t g_Wsw_bi[2 * 64 * 32768];         // fp16 frag-swizzled W_hh fwd/bwd
__device__ uint32_t g_Wsw_c[128 * 16384];             // fp16 frag-swizzled W_hh cell

__device__ unsigned g_barc[2] = {0, 0};
__device__ unsigned g_barg[2] = {0, 0};

__device__ __forceinline__ void grid_barrier(int which, unsigned nb) {
    __syncthreads();
    if (threadIdx.x == 0) {
        __threadfence();
        volatile unsigned* gen = &g_barg[which];
        unsigned g = *gen;
        if (atomicAdd(&g_barc[which], 1) == nb - 1) {
            g_barc[which] = 0;
            __threadfence();
            atomicExch((unsigned*)gen, g + 1);
        } else {
            while (*gen == g) { __nanosleep(64); }
            __threadfence();
        }
    }
    __syncthreads();
}

__global__ void zero_state_kernel() {
    int i = blockIdx.x * blockDim.x + threadIdx.x;
    if (i < 6 * B_ * N_ / 2) ((uint32_t*)g_h16)[i] = 0;   // 2 halves per u32
    if (i < 3 * B_ * N_) ((float*)g_c)[i] = 0.0f;
}

// ---------------- mma / cp.async helpers ----------------
__device__ __forceinline__ void mma_f16(float* c, const uint32_t* a, const uint32_t* b) {
    asm volatile(
        "mma.sync.aligned.m16n8k16.row.col.f32.f16.f16.f32 "
        "{%0,%1,%2,%3}, {%4,%5,%6,%7}, {%8,%9}, {%0,%1,%2,%3};"
        : "+f"(c[0]), "+f"(c[1]), "+f"(c[2]), "+f"(c[3])
        : "r"(a[0]), "r"(a[1]), "r"(a[2]), "r"(a[3]), "r"(b[0]), "r"(b[1]));
}
__device__ __forceinline__ void cp16(uint32_t dst, const void* src) {
    asm volatile("cp.async.cg.shared.global [%0], [%1], 16;" :: "r"(dst), "l"(src));
}
__device__ __forceinline__ void cp_commit() { asm volatile("cp.async.commit_group;"); }
template <int NN> __device__ __forceinline__ void cp_wait() {
    asm volatile("cp.async.wait_group %0;" :: "n"(NN));
}
__device__ __forceinline__ uint32_t pack2h(float a, float b) {
    __half2 h = __floats2half2_rn(a, b);
    return *(uint32_t*)&h;
}

// ---------------- one-time conversions ----------------
// x: [B,T,N] fp32 -> fp16 (8M float4 tasks)
__global__ void xconv_kernel(const float* __restrict__ x) {
    size_t i = (size_t)blockIdx.x * blockDim.x + threadIdx.x;
    float4 v = ((const float4*)x)[i];
    uint2 o;
    o.x = pack2h(v.x, v.y);
    o.y = pack2h(v.z, v.w);
    ((uint2*)g_x16)[i] = o;
}
// W_ih: 4M float4 tasks: [0,1M) f, [1M,2M) b, [2M,4M) c
__global__ void wconv_ih_kernel(const float* __restrict__ Wf,
                                const float* __restrict__ Wb,
                                const float* __restrict__ Wc) {
    size_t i = (size_t)blockIdx.x * blockDim.x + threadIdx.x;
    const float* src;
    size_t off;
    if (i < (1u << 20))      { src = Wf; off = i; }
    else if (i < (2u << 20)) { src = Wb; off = i - (1u << 20); }
    else                     { src = Wc; off = i - (2u << 20); }
    float4 v = ((const float4*)src)[off];
    uint2 o;
    o.x = pack2h(v.x, v.y);
    o.y = pack2h(v.z, v.w);
    ((uint2*)g_Wih16)[i] = o;
}

// ---------------- one-time W_hh fragment swizzles (fp16) ----------------
// bilstm: idx(u32) = region*32768 + k16*512 + jn*64 + lane*2 + r
// element: col = jn*8 + (lane>>2); k = k16*16 + r*8 + (lane&3)*2 + p
__global__ void wswz_bi_kernel(const float* __restrict__ Wf,
                               const float* __restrict__ Wb) {
    size_t idx = (size_t)blockIdx.x * blockDim.x + threadIdx.x;
    unsigned region = idx >> 15;
    unsigned w = idx & 32767;
    int dir = region >> 6, ublk = region & 63;
    int k16 = w >> 9;
    int jn = (w >> 6) & 7;
    int lane = (w >> 1) & 31;
    int r = w & 1;
    int gid = lane >> 2, tig = lane & 3;
    int col = jn * 8 + gid;
    int gate = col >> 4, u = col & 15;
    int row = gate * N_ + ublk * 16 + u;
    int k = k16 * 16 + r * 8 + tig * 2;
    const float* W = dir ? Wb : Wf;
    g_Wsw_bi[idx] = pack2h(W[(size_t)row * N_ + k], W[(size_t)row * N_ + k + 1]);
}
// cell: idx(u32) = blk*16384 + k16*256 + nwq*64 + lane*2 + r
__global__ void wswz_cell_kernel(const float* __restrict__ Wc) {
    size_t idx = (size_t)blockIdx.x * blockDim.x + threadIdx.x;
    unsigned blk = idx >> 14;
    unsigned w = idx & 16383;
    int k16 = w >> 8;
    int nwq = (w >> 6) & 3;
    int lane = (w >> 1) & 31;
    int r = w & 1;
    int gid = lane >> 2, tig = lane & 3;
    int col = nwq * 8 + gid;
    int gate = col >> 3, u = col & 7;
    int row = gate * N_ + blk * 8 + u;
    int k = k16 * 16 + r * 8 + tig * 2;
    g_Wsw_c[idx] = pack2h(Wc[(size_t)row * N_ + k], Wc[(size_t)row * N_ + k + 1]);
}

// ---------------- fp16 GEMM: 128x128x32, cp.async double buffered ----------------
// C[m][g] = sum_k A[m][k]*W[g][k] + bias[g]; A, W fp16.
// a_mode==1: m=(t*64+b) -> A row (b*512+t) (x16). a_mode==0: row m (g_bi16).
__global__ __launch_bounds__(256, 2) void gemm_f16_kernel(
    const __half* __restrict__ A,
    const __half* __restrict__ Wt,
    const float* __restrict__ bias,
    int K, int a_mode, int dst_sel)
{
    float* C = (dst_sel == 0) ? g_Pf : (dst_sel == 1) ? g_Pb : g_Pc;

    __shared__ __align__(16) uint32_t As[2][128 * 20];  // 32 fp16 (16 u32) + 4 pad
    __shared__ __align__(16) uint32_t Ws[2][128 * 20];

    const int tid = threadIdx.x;
    const int m0 = blockIdx.y * 128;
    const int g0 = blockIdx.x * 128;

    // loaders: 128 rows x 64B -> 512 cp16; 2 per thread. idx = tid + 256*i
    const __half* asrc[2];
    const __half* wsrc[2];
    int lrow[2], lseg[2];
#pragma unroll
    for (int i = 0; i < 2; i++) {
        int idx = tid + 256 * i;
        int row = idx >> 2;
        int seg = idx & 3;
        int m = m0 + row;
        int prow = (a_mode == 1) ? ((m & 63) * T_ + (m >> 6)) : m;
        asrc[i] = A + (size_t)prow * K + seg * 8;
        wsrc[i] = Wt + (size_t)(g0 + row) * K + seg * 8;
        lrow[i] = row; lseg[i] = seg;
    }
    uint32_t asm_a[2][2], wsm_a[2][2];
#pragma unroll
    for (int b = 0; b < 2; b++)
#pragma unroll
        for (int i = 0; i < 2; i++) {
            asm_a[b][i] = (uint32_t)__cvta_generic_to_shared(&As[b][lrow[i] * 20 + lseg[i] * 4]);
            wsm_a[b][i] = (uint32_t)__cvta_generic_to_shared(&Ws[b][lrow[i] * 20 + lseg[i] * 4]);
        }

    const int lane = tid & 31;
    const int wid = tid >> 5;
    const int gid = lane >> 2;
    const int tig = lane & 3;
    const int wm = (wid & 3) * 32;
    const int wn = (wid >> 2) * 64;

    float acc[2][8][4];
#pragma unroll
    for (int mf = 0; mf < 2; mf++)
#pragma unroll
        for (int nf = 0; nf < 8; nf++)
#pragma unroll
            for (int j = 0; j < 4; j++) acc[mf][nf][j] = 0.0f;

    const int NC = K / 32;
#pragma unroll
    for (int i = 0; i < 2; i++) {
        cp16(asm_a[0][i], asrc[i]);
        cp16(wsm_a[0][i], wsrc[i]);
    }
    cp_commit();

    for (int ch = 0; ch < NC; ch++) {
        const int buf = ch & 1;
        if (ch + 1 < NC) {
            const int nb = (ch + 1) & 1;
            const int k0 = (ch + 1) * 32;
#pragma unroll
            for (int i = 0; i < 2; i++) {
                cp16(asm_a[nb][i], asrc[i] + k0);
                cp16(wsm_a[nb][i], wsrc[i] + k0);
            }
            cp_commit();
            cp_wait<1>();
        } else {
            cp_wait<0>();
        }
        __syncthreads();

        const uint32_t* Af = As[buf];
        const uint32_t* Wf = Ws[buf];
#pragma unroll
        for (int ks = 0; ks < 2; ks++) {
            const int kb = ks * 8;
            uint32_t af[2][4];
#pragma unroll
            for (int mf = 0; mf < 2; mf++) {
                int mb = wm + mf * 16;
                af[mf][0] = Af[(mb + gid) * 20 + kb + tig];
                af[mf][1] = Af[(mb + gid + 8) * 20 + kb + tig];
                af[mf][2] = Af[(mb + gid) * 20 + kb + 4 + tig];
                af[mf][3] = Af[(mb + gid + 8) * 20 + kb + 4 + tig];
            }
            uint32_t bf[8][2];
#pragma unroll
            for (int nf = 0; nf < 8; nf++) {
                int nb2 = wn + nf * 8 + gid;
                bf[nf][0] = Wf[nb2 * 20 + kb + tig];
                bf[nf][1] = Wf[nb2 * 20 + kb + 4 + tig];
            }
#pragma unroll
            for (int mf = 0; mf < 2; mf++)
#pragma unroll
                for (int nf = 0; nf < 8; nf++)
                    mma_f16(acc[mf][nf], af[mf], bf[nf]);
        }
        __syncthreads();
    }

#pragma unroll
    for (int mf = 0; mf < 2; mf++) {
#pragma unroll
        for (int nf = 0; nf < 8; nf++) {
            int row = m0 + wm + mf * 16 + gid;
            int col = g0 + wn + nf * 8 + 2 * tig;
            float b0 = bias[col], b1 = bias[col + 1];
            float2 v0 = make_float2(acc[mf][nf][0] + b0, acc[mf][nf][1] + b1);
            float2 v1 = make_float2(acc[mf][nf][2] + b0, acc[mf][nf][3] + b1);
            *(float2*)&C[(size_t)row * G_ + col] = v0;
            *(float2*)&C[(size_t)(row + 8) * G_ + col] = v1;
        }
    }
}

// ---------------- persistent bilstm recurrence (fp16) ----------------
// 128 blocks x 512 threads (16 warps): wm=(wid&1)*32, jn=wid>>1 (n8 each).
__global__ __launch_bounds__(512, 1) void bilstm_mma_kernel()
{
    extern __shared__ uint32_t smem_u[];
    uint32_t* hs[2] = { smem_u, smem_u + 64 * SPH };
    float* gates = (float*)(smem_u + 2 * 64 * SPH);      // [64][68]

    const int bid = blockIdx.x;
    const int dir = bid >> 6;
    const int u0 = (bid & 63) * 16;
    const float* Pbase = dir ? g_Pb : g_Pf;
    float* c = g_c[dir];

    const int tid = threadIdx.x;
    const int lane = tid & 31;
    const int wid = tid >> 5;
    const int gid = lane >> 2;
    const int tig = lane & 3;
    const int wm = (wid & 1) * 32;
    const int jn = wid >> 1;
    const int wn = jn * 8;

    const uint32_t* wp = g_Wsw_bi + ((size_t)(dir * 64 + (bid & 63)) << 15)
                       + jn * 64 + lane * 2;

    // staging: 2 cp16/thread/chunk: rows r0, r0+32; seg tid&15 (16B segs of 256B row)
    const int r0 = tid >> 4;
    const int seg = tid & 15;
    uint32_t hs_a[2][2];
#pragma unroll
    for (int b = 0; b < 2; b++) {
        hs_a[b][0] = (uint32_t)__cvta_generic_to_shared(hs[b]) + (r0 * SPH + seg * 4) * 4;
        hs_a[b][1] = (uint32_t)__cvta_generic_to_shared(hs[b]) + ((r0 + 32) * SPH + seg * 4) * 4;
    }

    for (int s = 0; s < T_; s++) {
        const int t = dir ? (T_ - 1 - s) : s;
        const float* P = Pbase + (size_t)t * B_ * G_;
        const __half* h_prev = g_h16[2 * dir + (s & 1)];
        __half* h_next = g_h16[2 * dir + ((s + 1) & 1)];
        __half* hist = g_bi16 + (size_t)t * B_ * 2 * N_ + dir * N_;

        // preload chunk 0
        cp16(hs_a[0][0], h_prev + (size_t)r0 * N_ + seg * 8);
        cp16(hs_a[0][1], h_prev + (size_t)(r0 + 32) * N_ + seg * 8);
        cp_commit();

        uint2 wcur[8], wnext[8];
#pragma unroll
        for (int l = 0; l < 8; l++)
            wcur[l] = *(const uint2*)(wp + (size_t)l * 512);

        float acc[2][4];
#pragma unroll
        for (int mf = 0; mf < 2; mf++)
#pragma unroll
            for (int j = 0; j < 4; j++) acc[mf][j] = 0.0f;

        for (int ch = 0; ch < 8; ch++) {
            const int buf = ch & 1;
            if (ch + 1 < 8) {
                int ko = (ch + 1) * 128;
                cp16(hs_a[buf ^ 1][0], h_prev + (size_t)r0 * N_ + ko + seg * 8);
                cp16(hs_a[buf ^ 1][1], h_prev + (size_t)(r0 + 32) * N_ + ko + seg * 8);
                cp_commit();
                cp_wait<1>();
            } else {
                cp_wait<0>();
            }
            __syncthreads();

            if (ch + 1 < 8) {
#pragma unroll
                for (int l = 0; l < 8; l++)
                    wnext[l] = *(const uint2*)(wp + (size_t)((ch + 1) * 8 + l) * 512);
            }

            const uint32_t* Hu = hs[buf];
#pragma unroll
            for (int l = 0; l < 8; l++) {
                const int kb = l * 8;
                uint32_t af[2][4];
#pragma unroll
                for (int mf = 0; mf < 2; mf++) {
                    int mb = wm + mf * 16;
                    af[mf][0] = Hu[(mb + gid) * SPH + kb + tig];
                    af[mf][1] = Hu[(mb + gid + 8) * SPH + kb + tig];
                    af[mf][2] = Hu[(mb + gid) * SPH + kb + 4 + tig];
                    af[mf][3] = Hu[(mb + gid + 8) * SPH + kb + 4 + tig];
                }
                uint32_t bf[2] = { wcur[l].x, wcur[l].y };
#pragma unroll
                for (int mf = 0; mf < 2; mf++)
                    mma_f16(acc[mf], af[mf], bf);
            }
            if (ch + 1 < 8) {
#pragma unroll
                for (int l = 0; l < 8; l++) wcur[l] = wnext[l];
            }
            __syncthreads();
        }

#pragma unroll
        for (int mf = 0; mf < 2; mf++) {
            int row = wm + mf * 16 + gid;
            int col = wn + 2 * tig;
            gates[row * 68 + col]           = acc[mf][0];
            gates[row * 68 + col + 1]       = acc[mf][1];
            gates[(row + 8) * 68 + col]     = acc[mf][2];
            gates[(row + 8) * 68 + col + 1] = acc[mf][3];
        }
        __syncthreads();

        // activation: 64 b x 16 u -> 2 per thread
#pragma unroll
        for (int i = 0; i < 2; i++) {
            int p = tid + 512 * i;
            int bl = p >> 4;
            int u = p & 15;
            int ug = u0 + u;
            const float* Pb = P + (size_t)bl * G_;
            float ig = gates[bl * 68 + u]      + Pb[ug];
            float fg = gates[bl * 68 + 16 + u] + Pb[N_ + ug];
            float gg = gates[bl * 68 + 32 + u] + Pb[2 * N_ + ug];
            float og = gates[bl * 68 + 48 + u] + Pb[3 * N_ + ug];
            ig = 1.0f / (1.0f + expf(-ig));
            fg = 1.0f / (1.0f + expf(-fg));
            gg = tanhf(gg);
            og = 1.0f / (1.0f + expf(-og));
            size_t ci = (size_t)bl * N_ + ug;
            float cn = fg * c[ci] + ig * gg;
            c[ci] = cn;
            __half hn = __float2half_rn(og * tanhf(cn));
            h_next[ci] = hn;
            hist[(size_t)bl * 2 * N_ + ug] = hn;
        }
        grid_barrier(0, 128);
    }
}

// ---------------- persistent cell recurrence (fp16) ----------------
// 128 blocks x 512 threads: kh=wid>>3 (k halves), w8: wm=(w8&1)*32, nwq=w8>>1 (n8).
__global__ __launch_bounds__(512, 1) void cell_mma_kernel(float* __restrict__ out)
{
    extern __shared__ uint32_t smem_u[];
    uint32_t* hsb[2][2] = {
        { smem_u,                smem_u + 64 * SPH },
        { smem_u + 2 * 64 * SPH, smem_u + 3 * 64 * SPH }
    };
    float* gates0 = (float*)(smem_u + 4 * 64 * SPH);   // [64][36]
    float* gates1 = gates0 + 64 * 36;

    const int bid = blockIdx.x;
    const int u0 = bid * 8;
    float* c = g_c[2];

    const int tid = threadIdx.x;
    const int lane = tid & 31;
    const int wid = tid >> 5;
    const int gid = lane >> 2;
    const int tig = lane & 3;
    const int kh = wid >> 3;
    const int w8 = wid & 7;
    const int wm = (w8 & 1) * 32;
    const int nwq = w8 >> 1;
    const int wn = nwq * 8;

    const uint32_t* wp = g_Wsw_c + ((size_t)bid << 14) + nwq * 64 + lane * 2;
    const int k16base = kh * 32;

    const int r0 = tid >> 4;
    const int seg = tid & 15;
    uint32_t hs_a[2][2][2];   // [buf][half][rowgrp]
#pragma unroll
    for (int b = 0; b < 2; b++)
#pragma unroll
        for (int hh = 0; hh < 2; hh++) {
            hs_a[b][hh][0] = (uint32_t)__cvta_generic_to_shared(hsb[b][hh]) + (r0 * SPH + seg * 4) * 4;
            hs_a[b][hh][1] = (uint32_t)__cvta_generic_to_shared(hsb[b][hh]) + ((r0 + 32) * SPH + seg * 4) * 4;
        }

    for (int s = 0; s < T_; s++) {
        const float* P = g_Pc + (size_t)s * B_ * G_;
        const __half* h_prev = g_h16[4 + (s & 1)];
        __half* h_next = g_h16[4 + ((s + 1) & 1)];

        // preload chunk 0 for both k halves
#pragma unroll
        for (int hh = 0; hh < 2; hh++) {
            cp16(hs_a[0][hh][0], h_prev + (size_t)r0 * N_ + hh * 512 + seg * 8);
            cp16(hs_a[0][hh][1], h_prev + (size_t)(r0 + 32) * N_ + hh * 512 + seg * 8);
        }
        cp_commit();

        uint2 wcur[8], wnext[8];
#pragma unroll
        for (int l = 0; l < 8; l++)
            wcur[l] = *(const uint2*)(wp + (size_t)(k16base + l) * 256);

        float acc[2][4];
#pragma unroll
        for (int mf = 0; mf < 2; mf++)
#pragma unroll
            for (int j = 0; j < 4; j++) acc[mf][j] = 0.0f;

        for (int ch = 0; ch < 4; ch++) {
            const int buf = ch & 1;
            if (ch + 1 < 4) {
                int ko = (ch + 1) * 128;
#pragma unroll
                for (int hh = 0; hh < 2; hh++) {
                    cp16(hs_a[buf ^ 1][hh][0], h_prev + (size_t)r0 * N_ + hh * 512 + ko + seg * 8);
                    cp16(hs_a[buf ^ 1][hh][1], h_prev + (size_t)(r0 + 32) * N_ + hh * 512 + ko + seg * 8);
                }
                cp_commit();
                cp_wait<1>();
            } else {
                cp_wait<0>();
            }
            __syncthreads();

            if (ch + 1 < 4) {
#pragma unroll
                for (int l = 0; l < 8; l++)
                    wnext[l] = *(const uint2*)(wp + (size_t)(k16base + (ch + 1) * 8 + l) * 256);
            }

            const uint32_t* Hu = hsb[buf][kh];
#pragma unroll
            for (int l = 0; l < 8; l++) {
                const int kb = l * 8;
                uint32_t af[2][4];
#pragma unroll
                for (int mf = 0; mf < 2; mf++) {
                    int mb = wm + mf * 16;
                    af[mf][0] = Hu[(mb + gid) * SPH + kb + tig];
                    af[mf][1] = Hu[(mb + gid + 8) * SPH + kb + tig];
                    af[mf][2] = Hu[(mb + gid) * SPH + kb + 4 + tig];
                    af[mf][3] = Hu[(mb + gid + 8) * SPH + kb + 4 + tig];
                }
                uint32_t bf[2] = { wcur[l].x, wcur[l].y };
#pragma unroll
                for (int mf = 0; mf < 2; mf++)
                    mma_f16(acc[mf], af[mf], bf);
            }
            if (ch + 1 < 4) {
#pragma unroll
                for (int l = 0; l < 8; l++) wcur[l] = wnext[l];
            }
            __syncthreads();
        }

        float* G = kh ? gates1 : gates0;
#pragma unroll
        for (int mf = 0; mf < 2; mf++) {
            int row = wm + mf * 16 + gid;
            int col = wn + 2 * tig;
            G[row * 36 + col]           = acc[mf][0];
            G[row * 36 + col + 1]       = acc[mf][1];
            G[(row + 8) * 36 + col]     = acc[mf][2];
            G[(row + 8) * 36 + col + 1] = acc[mf][3];
        }
        __syncthreads();

        // activation: 64 b x 8 u -> 1 per thread
        {
            int bl = tid >> 3;
            int u = tid & 7;
            int ug = u0 + u;
            const float* Pb = P + (size_t)bl * G_;
            float ig = gates0[bl * 36 + u]      + gates1[bl * 36 + u]      + Pb[ug];
            float fg = gates0[bl * 36 + 8 + u]  + gates1[bl * 36 + 8 + u]  + Pb[N_ + ug];
            float gg = gates0[bl * 36 + 16 + u] + gates1[bl * 36 + 16 + u] + Pb[2 * N_ + ug];
            float og = gates0[bl * 36 + 24 + u] + gates1[bl * 36 + 24 + u] + Pb[3 * N_ + ug];
            ig = 1.0f / (1.0f + expf(-ig));
            fg = 1.0f / (1.0f + expf(-fg));
            gg = tanhf(gg);
            og = 1.0f / (1.0f + expf(-og));
            size_t ci = (size_t)bl * N_ + ug;
            float cn = fg * c[ci] + ig * gg;
            c[ci] = cn;
            float hn = og * tanhf(cn);
            out[((size_t)bl * T_ + s) * N_ + ug] = hn;
            h_next[ci] = __float2half_rn(hn);
            if (s == T_ - 1) {
                const size_t tail = (size_t)B_ * T_ * N_;
                out[tail + ci] = hn;
                out[tail + (size_t)B_ * N_ + ci] = cn;
            }
        }
        grid_barrier(1, 128);
    }
}

// ---------------- host launcher ----------------
extern "C" void kernel_launch(void* const* d_in, const int* in_sizes, int n_in,
                              void* d_out, int out_size) {
    (void)in_sizes; (void)n_in; (void)out_size;
    const float* x     = (const float*)d_in[0];
    const float* Wf_ih = (const float*)d_in[1];
    const float* Wf_hh = (const float*)d_in[2];
    const float* bf    = (const float*)d_in[3];
    const float* Wb_ih = (const float*)d_in[4];
    const float* Wb_hh = (const float*)d_in[5];
    const float* bb    = (const float*)d_in[6];
    const float* Wc_ih = (const float*)d_in[7];
    const float* Wc_hh = (const float*)d_in[8];
    const float* bc    = (const float*)d_in[9];
    float* out = (float*)d_out;

    __half *wih, *x16, *bi16;
    cudaGetSymbolAddress((void**)&wih, g_Wih16);
    cudaGetSymbolAddress((void**)&x16, g_x16);
    cudaGetSymbolAddress((void**)&bi16, g_bi16);
    const __half* wih_f = wih;
    const __half* wih_b = wih + (4u << 20);
    const __half* wih_c = wih + (8u << 20);

    const int bilstm_smem = 2 * 64 * SPH * 4 + 64 * 68 * 4;      // 52224
    const int cell_smem   = 4 * 64 * SPH * 4 + 2 * 64 * 36 * 4;  // 88064
    cudaFuncSetAttribute(bilstm_mma_kernel, cudaFuncAttributeMaxDynamicSharedMemorySize, bilstm_smem);
    cudaFuncSetAttribute(cell_mma_kernel, cudaFuncAttributeMaxDynamicSharedMemorySize, cell_smem);

    // 1) init + one-time conversions/swizzles
    zero_state_kernel<<<(3 * B_ * N_ + 511) / 512, 512>>>();
    xconv_kernel<<<(8 << 20) / 256, 256>>>(x);
    wconv_ih_kernel<<<(4 << 20) / 256, 256>>>(Wf_ih, Wb_ih, Wc_ih);
    wswz_bi_kernel<<<(4 << 20) / 256, 256>>>(Wf_hh, Wb_hh);
    wswz_cell_kernel<<<(2 << 20) / 256, 256>>>(Wc_hh);

    // 2) input projections (fp16 mma)
    dim3 ggrid(G_ / 128, (T_ * B_) / 128);
    gemm_f16_kernel<<<ggrid, 256>>>(x16, wih_f, bf, N_, 1, 0);
    gemm_f16_kernel<<<ggrid, 256>>>(x16, wih_b, bb, N_, 1, 1);

    // 3) bilstm recurrence
    bilstm_mma_kernel<<<128, 512, bilstm_smem>>>();

    // 4) cell input projection (K = 2N, A = g_bi16)
    gemm_f16_kernel<<<ggrid, 256>>>(bi16, wih_c, bc, 2 * N_, 0, 2);

    // 5) cell recurrence + output (+ hT/cT tail at final step)
    cell_mma_kernel<<<128, 512, cell_smem>>>(out);
}

// round 7
// speedup vs baseline: 1.9263x; 1.1538x over previous
#include <cuda_runtime.h>
#include <cuda_fp16.h>
#include <cstdint>
#include <math.h>

#define T_ 512
#define B_ 64
#define N_ 1024
#define G_ 4096   // 4*N
#define SPH 68    // smem pitch (u32) for fp16 h tiles (128 fp16 = 64 u32 + 4 pad)

// ---------------- static device scratch ----------------
__device__ float g_Pf[(size_t)T_ * B_ * G_];
__device__ float g_Pb[(size_t)T_ * B_ * G_];
__device__ float g_Pc[(size_t)T_ * B_ * G_];
__device__ __half g_bi16[(size_t)T_ * B_ * 2 * N_];   // bilstm output, fp16
__device__ __half g_x16[(size_t)B_ * T_ * N_];        // inputs converted to fp16
__device__ __half g_Wih16[16 * 1024 * 1024];          // fp16 W_ih: f(4M) b(4M) c(8M)
__device__ __half g_h16[6][B_ * N_];                  // fp16 recurrent h
__device__ float  g_c[3][B_ * N_];                    // fp32 cell state
__device__ uint32_t g_Wsw_bi[2 * 64 * 32768];         // fp16 frag-swizzled W_hh fwd/bwd
__device__ uint32_t g_Wsw_c[128 * 16384];             // fp16 frag-swizzled W_hh cell

__device__ unsigned g_barc[2] = {0, 0};
__device__ unsigned g_barg[2] = {0, 0};

__device__ __forceinline__ void grid_barrier(int which, unsigned nb) {
    __syncthreads();
    if (threadIdx.x == 0) {
        __threadfence();
        volatile unsigned* gen = &g_barg[which];
        unsigned g = *gen;
        if (atomicAdd(&g_barc[which], 1) == nb - 1) {
            g_barc[which] = 0;
            __threadfence();
            atomicExch((unsigned*)gen, g + 1);
        } else {
            while (*gen == g) { }
            __threadfence();
        }
    }
    __syncthreads();
}

__global__ void zero_state_kernel() {
    int i = blockIdx.x * blockDim.x + threadIdx.x;
    if (i < 6 * B_ * N_ / 2) ((uint32_t*)g_h16)[i] = 0;
    if (i < 3 * B_ * N_) ((float*)g_c)[i] = 0.0f;
}

// ---------------- mma / cp.async / ldmatrix helpers ----------------
__device__ __forceinline__ void mma_f16(float* c, const uint32_t* a, const uint32_t* b) {
    asm volatile(
        "mma.sync.aligned.m16n8k16.row.col.f32.f16.f16.f32 "
        "{%0,%1,%2,%3}, {%4,%5,%6,%7}, {%8,%9}, {%0,%1,%2,%3};"
        : "+f"(c[0]), "+f"(c[1]), "+f"(c[2]), "+f"(c[3])
        : "r"(a[0]), "r"(a[1]), "r"(a[2]), "r"(a[3]), "r"(b[0]), "r"(b[1]));
}
__device__ __forceinline__ void ldsm_x4(uint32_t& r0, uint32_t& r1, uint32_t& r2, uint32_t& r3,
                                        uint32_t addr) {
    asm volatile("ldmatrix.sync.aligned.m8n8.x4.shared.b16 {%0,%1,%2,%3}, [%4];"
                 : "=r"(r0), "=r"(r1), "=r"(r2), "=r"(r3) : "r"(addr));
}
__device__ __forceinline__ void cp16(uint32_t dst, const void* src) {
    asm volatile("cp.async.cg.shared.global [%0], [%1], 16;" :: "r"(dst), "l"(src));
}
__device__ __forceinline__ void cp_commit() { asm volatile("cp.async.commit_group;"); }
template <int NN> __device__ __forceinline__ void cp_wait() {
    asm volatile("cp.async.wait_group %0;" :: "n"(NN));
}
__device__ __forceinline__ uint32_t pack2h(float a, float b) {
    __half2 h = __floats2half2_rn(a, b);
    return *(uint32_t*)&h;
}

// ---------------- one-time conversions ----------------
__global__ void xconv_kernel(const float* __restrict__ x) {
    size_t i = (size_t)blockIdx.x * blockDim.x + threadIdx.x;
    float4 v = ((const float4*)x)[i];
    uint2 o;
    o.x = pack2h(v.x, v.y);
    o.y = pack2h(v.z, v.w);
    ((uint2*)g_x16)[i] = o;
}
__global__ void wconv_ih_kernel(const float* __restrict__ Wf,
                                const float* __restrict__ Wb,
                                const float* __restrict__ Wc) {
    size_t i = (size_t)blockIdx.x * blockDim.x + threadIdx.x;
    const float* src;
    size_t off;
    if (i < (1u << 20))      { src = Wf; off = i; }
    else if (i < (2u << 20)) { src = Wb; off = i - (1u << 20); }
    else                     { src = Wc; off = i - (2u << 20); }
    float4 v = ((const float4*)src)[off];
    uint2 o;
    o.x = pack2h(v.x, v.y);
    o.y = pack2h(v.z, v.w);
    ((uint2*)g_Wih16)[i] = o;
}

// ---------------- one-time W_hh fragment swizzles (fp16) ----------------
// bilstm: idx(u32) = region*32768 + k16*512 + jn*64 + lane*2 + r
__global__ void wswz_bi_kernel(const float* __restrict__ Wf,
                               const float* __restrict__ Wb) {
    size_t idx = (size_t)blockIdx.x * blockDim.x + threadIdx.x;
    unsigned region = idx >> 15;
    unsigned w = idx & 32767;
    int dir = region >> 6, ublk = region & 63;
    int k16 = w >> 9;
    int jn = (w >> 6) & 7;
    int lane = (w >> 1) & 31;
    int r = w & 1;
    int gid = lane >> 2, tig = lane & 3;
    int col = jn * 8 + gid;
    int gate = col >> 4, u = col & 15;
    int row = gate * N_ + ublk * 16 + u;
    int k = k16 * 16 + r * 8 + tig * 2;
    const float* W = dir ? Wb : Wf;
    g_Wsw_bi[idx] = pack2h(W[(size_t)row * N_ + k], W[(size_t)row * N_ + k + 1]);
}
// cell: idx(u32) = blk*16384 + k16*256 + nwq*64 + lane*2 + r
__global__ void wswz_cell_kernel(const float* __restrict__ Wc) {
    size_t idx = (size_t)blockIdx.x * blockDim.x + threadIdx.x;
    unsigned blk = idx >> 14;
    unsigned w = idx & 16383;
    int k16 = w >> 8;
    int nwq = (w >> 6) & 3;
    int lane = (w >> 1) & 31;
    int r = w & 1;
    int gid = lane >> 2, tig = lane & 3;
    int col = nwq * 8 + gid;
    int gate = col >> 3, u = col & 7;
    int row = gate * N_ + blk * 8 + u;
    int k = k16 * 16 + r * 8 + tig * 2;
    g_Wsw_c[idx] = pack2h(Wc[(size_t)row * N_ + k], Wc[(size_t)row * N_ + k + 1]);
}

// ---------------- fp16 GEMM: 128x128x32, cp.async double buffered, ldmatrix ----------------
__global__ __launch_bounds__(256, 2) void gemm_f16_kernel(
    const __half* __restrict__ A,
    const __half* __restrict__ Wt,
    const float* __restrict__ bias,
    int K, int a_mode, int dst_sel)
{
    float* C = (dst_sel == 0) ? g_Pf : (dst_sel == 1) ? g_Pb : g_Pc;

    __shared__ __align__(16) uint32_t As[2][128 * 20];  // 32 fp16 (16 u32) + 4 pad
    __shared__ __align__(16) uint32_t Ws[2][128 * 20];

    const int tid = threadIdx.x;
    const int m0 = blockIdx.y * 128;
    const int g0 = blockIdx.x * 128;

    const __half* asrc[2];
    const __half* wsrc[2];
    int lrow[2], lseg[2];
#pragma unroll
    for (int i = 0; i < 2; i++) {
        int idx = tid + 256 * i;
        int row = idx >> 2;
        int seg = idx & 3;
        int m = m0 + row;
        int prow = (a_mode == 1) ? ((m & 63) * T_ + (m >> 6)) : m;
        asrc[i] = A + (size_t)prow * K + seg * 8;
        wsrc[i] = Wt + (size_t)(g0 + row) * K + seg * 8;
        lrow[i] = row; lseg[i] = seg;
    }
    uint32_t asm_a[2][2], wsm_a[2][2];
#pragma unroll
    for (int b = 0; b < 2; b++)
#pragma unroll
        for (int i = 0; i < 2; i++) {
            asm_a[b][i] = (uint32_t)__cvta_generic_to_shared(&As[b][lrow[i] * 20 + lseg[i] * 4]);
            wsm_a[b][i] = (uint32_t)__cvta_generic_to_shared(&Ws[b][lrow[i] * 20 + lseg[i] * 4]);
        }

    const int lane = tid & 31;
    const int wid = tid >> 5;
    const int gid = lane >> 2;
    const int tig = lane & 3;
    const int wm = (wid & 3) * 32;
    const int wn = (wid >> 2) * 64;

    // ldmatrix per-lane geometry
    const int rowA = lane & 15;
    const int koffA = (lane >> 4) * 4;                 // u32 offset for k8..15
    const int cB = (lane & 7) + ((lane >> 4) << 3);    // col within 16-col pair
    const int kB = ((lane >> 3) & 1) * 4;

    uint32_t aaddr[2][2], baddr[2][4];
#pragma unroll
    for (int b = 0; b < 2; b++) {
#pragma unroll
        for (int mf = 0; mf < 2; mf++)
            aaddr[b][mf] = (uint32_t)__cvta_generic_to_shared(
                &As[b][(wm + mf * 16 + rowA) * 20 + koffA]);
#pragma unroll
        for (int np = 0; np < 4; np++)
            baddr[b][np] = (uint32_t)__cvta_generic_to_shared(
                &Ws[b][(wn + np * 16 + cB) * 20 + kB]);
    }

    float acc[2][8][4];
#pragma unroll
    for (int mf = 0; mf < 2; mf++)
#pragma unroll
        for (int nf = 0; nf < 8; nf++)
#pragma unroll
            for (int j = 0; j < 4; j++) acc[mf][nf][j] = 0.0f;

    const int NC = K / 32;
#pragma unroll
    for (int i = 0; i < 2; i++) {
        cp16(asm_a[0][i], asrc[i]);
        cp16(wsm_a[0][i], wsrc[i]);
    }
    cp_commit();

    for (int ch = 0; ch < NC; ch++) {
        const int buf = ch & 1;
        if (ch + 1 < NC) {
            const int nb = (ch + 1) & 1;
            const int k0 = (ch + 1) * 32;
#pragma unroll
            for (int i = 0; i < 2; i++) {
                cp16(asm_a[nb][i], asrc[i] + k0);
                cp16(wsm_a[nb][i], wsrc[i] + k0);
            }
            cp_commit();
            cp_wait<1>();
        } else {
            cp_wait<0>();
        }
        __syncthreads();

#pragma unroll
        for (int ks = 0; ks < 2; ks++) {
            const int kbb = ks * 32;    // byte offset (8 u32)
            uint32_t af[2][4];
#pragma unroll
            for (int mf = 0; mf < 2; mf++)
                ldsm_x4(af[mf][0], af[mf][1], af[mf][2], af[mf][3], aaddr[buf][mf] + kbb);
            uint32_t bf[8][2];
#pragma unroll
            for (int np = 0; np < 4; np++)
                ldsm_x4(bf[2 * np][0], bf[2 * np][1], bf[2 * np + 1][0], bf[2 * np + 1][1],
                        baddr[buf][np] + kbb);
#pragma unroll
            for (int mf = 0; mf < 2; mf++)
#pragma unroll
                for (int nf = 0; nf < 8; nf++)
                    mma_f16(acc[mf][nf], af[mf], bf[nf]);
        }
        __syncthreads();
    }

#pragma unroll
    for (int mf = 0; mf < 2; mf++) {
#pragma unroll
        for (int nf = 0; nf < 8; nf++) {
            int row = m0 + wm + mf * 16 + gid;
            int col = g0 + wn + nf * 8 + 2 * tig;
            float b0 = bias[col], b1 = bias[col + 1];
            float2 v0 = make_float2(acc[mf][nf][0] + b0, acc[mf][nf][1] + b1);
            float2 v1 = make_float2(acc[mf][nf][2] + b0, acc[mf][nf][3] + b1);
            *(float2*)&C[(size_t)row * G_ + col] = v0;
            *(float2*)&C[(size_t)(row + 8) * G_ + col] = v1;
        }
    }
}

// ---------------- persistent bilstm recurrence (fp16, ldmatrix) ----------------
__global__ __launch_bounds__(512, 1) void bilstm_mma_kernel()
{
    extern __shared__ uint32_t smem_u[];
    uint32_t* hs[2] = { smem_u, smem_u + 64 * SPH };
    float* gates = (float*)(smem_u + 2 * 64 * SPH);      // [64][68]

    const int bid = blockIdx.x;
    const int dir = bid >> 6;
    const int u0 = (bid & 63) * 16;
    const float* Pbase = dir ? g_Pb : g_Pf;
    float* c = g_c[dir];

    const int tid = threadIdx.x;
    const int lane = tid & 31;
    const int wid = tid >> 5;
    const int gid = lane >> 2;
    const int tig = lane & 3;
    const int wm = (wid & 1) * 32;
    const int jn = wid >> 1;
    const int wn = jn * 8;

    const uint32_t* wp = g_Wsw_bi + ((size_t)(dir * 64 + (bid & 63)) << 15)
                       + jn * 64 + lane * 2;

    const int r0 = tid >> 4;
    const int seg = tid & 15;
    uint32_t hs_a[2][2];
#pragma unroll
    for (int b = 0; b < 2; b++) {
        hs_a[b][0] = (uint32_t)__cvta_generic_to_shared(hs[b]) + (r0 * SPH + seg * 4) * 4;
        hs_a[b][1] = (uint32_t)__cvta_generic_to_shared(hs[b]) + ((r0 + 32) * SPH + seg * 4) * 4;
    }

    // ldmatrix A-fragment addresses
    const int rowA = lane & 15;
    const int koffA = (lane >> 4) * 4;
    uint32_t haddr[2][2];
#pragma unroll
    for (int b = 0; b < 2; b++)
#pragma unroll
        for (int mf = 0; mf < 2; mf++)
            haddr[b][mf] = (uint32_t)__cvta_generic_to_shared(
                &hs[b][(wm + mf * 16 + rowA) * SPH + koffA]);

    for (int s = 0; s < T_; s++) {
        const int t = dir ? (T_ - 1 - s) : s;
        const float* P = Pbase + (size_t)t * B_ * G_;
        const __half* h_prev = g_h16[2 * dir + (s & 1)];
        __half* h_next = g_h16[2 * dir + ((s + 1) & 1)];
        __half* hist = g_bi16 + (size_t)t * B_ * 2 * N_ + dir * N_;

        cp16(hs_a[0][0], h_prev + (size_t)r0 * N_ + seg * 8);
        cp16(hs_a[0][1], h_prev + (size_t)(r0 + 32) * N_ + seg * 8);
        cp_commit();

        uint2 wcur[8], wnext[8];
#pragma unroll
        for (int l = 0; l < 8; l++)
            wcur[l] = *(const uint2*)(wp + (size_t)l * 512);

        float acc[2][4];
#pragma unroll
        for (int mf = 0; mf < 2; mf++)
#pragma unroll
            for (int j = 0; j < 4; j++) acc[mf][j] = 0.0f;

        for (int ch = 0; ch < 8; ch++) {
            const int buf = ch & 1;
            if (ch + 1 < 8) {
                int ko = (ch + 1) * 128;
                cp16(hs_a[buf ^ 1][0], h_prev + (size_t)r0 * N_ + ko + seg * 8);
                cp16(hs_a[buf ^ 1][1], h_prev + (size_t)(r0 + 32) * N_ + ko + seg * 8);
                cp_commit();
                cp_wait<1>();
            } else {
                cp_wait<0>();
            }
            __syncthreads();

            if (ch + 1 < 8) {
#pragma unroll
                for (int l = 0; l < 8; l++)
                    wnext[l] = *(const uint2*)(wp + (size_t)((ch + 1) * 8 + l) * 512);
            }

#pragma unroll
            for (int l = 0; l < 8; l++) {
                uint32_t af[2][4];
#pragma unroll
                for (int mf = 0; mf < 2; mf++)
                    ldsm_x4(af[mf][0], af[mf][1], af[mf][2], af[mf][3],
                            haddr[buf][mf] + l * 32);
                uint32_t bf[2] = { wcur[l].x, wcur[l].y };
#pragma unroll
                for (int mf = 0; mf < 2; mf++)
                    mma_f16(acc[mf], af[mf], bf);
            }
            if (ch + 1 < 8) {
#pragma unroll
                for (int l = 0; l < 8; l++) wcur[l] = wnext[l];
            }
            __syncthreads();
        }

#pragma unroll
        for (int mf = 0; mf < 2; mf++) {
            int row = wm + mf * 16 + gid;
            int col = wn + 2 * tig;
            gates[row * 68 + col]           = acc[mf][0];
            gates[row * 68 + col + 1]       = acc[mf][1];
            gates[(row + 8) * 68 + col]     = acc[mf][2];
            gates[(row + 8) * 68 + col + 1] = acc[mf][3];
        }
        __syncthreads();

#pragma unroll
        for (int i = 0; i < 2; i++) {
            int p = tid + 512 * i;
            int bl = p >> 4;
            int u = p & 15;
            int ug = u0 + u;
            const float* Pb = P + (size_t)bl * G_;
            float ig = gates[bl * 68 + u]      + Pb[ug];
            float fg = gates[bl * 68 + 16 + u] + Pb[N_ + ug];
            float gg = gates[bl * 68 + 32 + u] + Pb[2 * N_ + ug];
            float og = gates[bl * 68 + 48 + u] + Pb[3 * N_ + ug];
            ig = 1.0f / (1.0f + expf(-ig));
            fg = 1.0f / (1.0f + expf(-fg));
            gg = tanhf(gg);
            og = 1.0f / (1.0f + expf(-og));
            size_t ci = (size_t)bl * N_ + ug;
            float cn = fg * c[ci] + ig * gg;
            c[ci] = cn;
            __half hn = __float2half_rn(og * tanhf(cn));
            h_next[ci] = hn;
            hist[(size_t)bl * 2 * N_ + ug] = hn;
        }
        grid_barrier(0, 128);
    }
}

// ---------------- persistent cell recurrence (fp16, ldmatrix) ----------------
__global__ __launch_bounds__(512, 1) void cell_mma_kernel(float* __restrict__ out)
{
    extern __shared__ uint32_t smem_u[];
    uint32_t* hsb[2][2] = {
        { smem_u,                smem_u + 64 * SPH },
        { smem_u + 2 * 64 * SPH, smem_u + 3 * 64 * SPH }
    };
    float* gates0 = (float*)(smem_u + 4 * 64 * SPH);   // [64][36]
    float* gates1 = gates0 + 64 * 36;

    const int bid = blockIdx.x;
    const int u0 = bid * 8;
    float* c = g_c[2];

    const int tid = threadIdx.x;
    const int lane = tid & 31;
    const int wid = tid >> 5;
    const int gid = lane >> 2;
    const int tig = lane & 3;
    const int kh = wid >> 3;
    const int w8 = wid & 7;
    const int wm = (w8 & 1) * 32;
    const int nwq = w8 >> 1;
    const int wn = nwq * 8;

    const uint32_t* wp = g_Wsw_c + ((size_t)bid << 14) + nwq * 64 + lane * 2;
    const int k16base = kh * 32;

    const int r0 = tid >> 4;
    const int seg = tid & 15;
    uint32_t hs_a[2][2][2];
#pragma unroll
    for (int b = 0; b < 2; b++)
#pragma unroll
        for (int hh = 0; hh < 2; hh++) {
            hs_a[b][hh][0] = (uint32_t)__cvta_generic_to_shared(hsb[b][hh]) + (r0 * SPH + seg * 4) * 4;
            hs_a[b][hh][1] = (uint32_t)__cvta_generic_to_shared(hsb[b][hh]) + ((r0 + 32) * SPH + seg * 4) * 4;
        }

    const int rowA = lane & 15;
    const int koffA = (lane >> 4) * 4;
    uint32_t haddr[2][2];
#pragma unroll
    for (int b = 0; b < 2; b++)
#pragma unroll
        for (int mf = 0; mf < 2; mf++)
            haddr[b][mf] = (uint32_t)__cvta_generic_to_shared(
                &hsb[b][kh][(wm + mf * 16 + rowA) * SPH + koffA]);

    for (int s = 0; s < T_; s++) {
        const float* P = g_Pc + (size_t)s * B_ * G_;
        const __half* h_prev = g_h16[4 + (s & 1)];
        __half* h_next = g_h16[4 + ((s + 1) & 1)];

#pragma unroll
        for (int hh = 0; hh < 2; hh++) {
            cp16(hs_a[0][hh][0], h_prev + (size_t)r0 * N_ + hh * 512 + seg * 8);
            cp16(hs_a[0][hh][1], h_prev + (size_t)(r0 + 32) * N_ + hh * 512 + seg * 8);
        }
        cp_commit();

        uint2 wcur[8], wnext[8];
#pragma unroll
        for (int l = 0; l < 8; l++)
            wcur[l] = *(const uint2*)(wp + (size_t)(k16base + l) * 256);

        float acc[2][4];
#pragma unroll
        for (int mf = 0; mf < 2; mf++)
#pragma unroll
            for (int j = 0; j < 4; j++) acc[mf][j] = 0.0f;

        for (int ch = 0; ch < 4; ch++) {
            const int buf = ch & 1;
            if (ch + 1 < 4) {
                int ko = (ch + 1) * 128;
#pragma unroll
                for (int hh = 0; hh < 2; hh++) {
                    cp16(hs_a[buf ^ 1][hh][0], h_prev + (size_t)r0 * N_ + hh * 512 + ko + seg * 8);
                    cp16(hs_a[buf ^ 1][hh][1], h_prev + (size_t)(r0 + 32) * N_ + hh * 512 + ko + seg * 8);
                }
                cp_commit();
                cp_wait<1>();
            } else {
                cp_wait<0>();
            }
            __syncthreads();

            if (ch + 1 < 4) {
#pragma unroll
                for (int l = 0; l < 8; l++)
                    wnext[l] = *(const uint2*)(wp + (size_t)(k16base + (ch + 1) * 8 + l) * 256);
            }

#pragma unroll
            for (int l = 0; l < 8; l++) {
                uint32_t af[2][4];
#pragma unroll
                for (int mf = 0; mf < 2; mf++)
                    ldsm_x4(af[mf][0], af[mf][1], af[mf][2], af[mf][3],
                            haddr[buf][mf] + l * 32);
                uint32_t bf[2] = { wcur[l].x, wcur[l].y };
#pragma unroll
                for (int mf = 0; mf < 2; mf++)
                    mma_f16(acc[mf], af[mf], bf);
            }
            if (ch + 1 < 4) {
#pragma unroll
                for (int l = 0; l < 8; l++) wcur[l] = wnext[l];
            }
            __syncthreads();
        }

        float* G = kh ? gates1 : gates0;
#pragma unroll
        for (int mf = 0; mf < 2; mf++) {
            int row = wm + mf * 16 + gid;
            int col = wn + 2 * tig;
            G[row * 36 + col]           = acc[mf][0];
            G[row * 36 + col + 1]       = acc[mf][1];
            G[(row + 8) * 36 + col]     = acc[mf][2];
            G[(row + 8) * 36 + col + 1] = acc[mf][3];
        }
        __syncthreads();

        {
            int bl = tid >> 3;
            int u = tid & 7;
            int ug = u0 + u;
            const float* Pb = P + (size_t)bl * G_;
            float ig = gates0[bl * 36 + u]      + gates1[bl * 36 + u]      + Pb[ug];
            float fg = gates0[bl * 36 + 8 + u]  + gates1[bl * 36 + 8 + u]  + Pb[N_ + ug];
            float gg = gates0[bl * 36 + 16 + u] + gates1[bl * 36 + 16 + u] + Pb[2 * N_ + ug];
            float og = gates0[bl * 36 + 24 + u] + gates1[bl * 36 + 24 + u] + Pb[3 * N_ + ug];
            ig = 1.0f / (1.0f + expf(-ig));
            fg = 1.0f / (1.0f + expf(-fg));
            gg = tanhf(gg);
            og = 1.0f / (1.0f + expf(-og));
            size_t ci = (size_t)bl * N_ + ug;
            float cn = fg * c[ci] + ig * gg;
            c[ci] = cn;
            float hn = og * tanhf(cn);
            out[((size_t)bl * T_ + s) * N_ + ug] = hn;
            h_next[ci] = __float2half_rn(hn);
            if (s == T_ - 1) {
                const size_t tail = (size_t)B_ * T_ * N_;
                out[tail + ci] = hn;
                out[tail + (size_t)B_ * N_ + ci] = cn;
            }
        }
        grid_barrier(1, 128);
    }
}

// ---------------- host launcher ----------------
extern "C" void kernel_launch(void* const* d_in, const int* in_sizes, int n_in,
                              void* d_out, int out_size) {
    (void)in_sizes; (void)n_in; (void)out_size;
    const float* x     = (const float*)d_in[0];
    const float* Wf_ih = (const float*)d_in[1];
    const float* Wf_hh = (const float*)d_in[2];
    const float* bf    = (const float*)d_in[3];
    const float* Wb_ih = (const float*)d_in[4];
    const float* Wb_hh = (const float*)d_in[5];
    const float* bb    = (const float*)d_in[6];
    const float* Wc_ih = (const float*)d_in[7];
    const float* Wc_hh = (const float*)d_in[8];
    const float* bc    = (const float*)d_in[9];
    float* out = (float*)d_out;

    __half *wih, *x16, *bi16;
    cudaGetSymbolAddress((void**)&wih, g_Wih16);
    cudaGetSymbolAddress((void**)&x16, g_x16);
    cudaGetSymbolAddress((void**)&bi16, g_bi16);
    const __half* wih_f = wih;
    const __half* wih_b = wih + (4u << 20);
    const __half* wih_c = wih + (8u << 20);

    const int bilstm_smem = 2 * 64 * SPH * 4 + 64 * 68 * 4;      // 52224
    const int cell_smem   = 4 * 64 * SPH * 4 + 2 * 64 * 36 * 4;  // 88064
    cudaFuncSetAttribute(bilstm_mma_kernel, cudaFuncAttributeMaxDynamicSharedMemorySize, bilstm_smem);
    cudaFuncSetAttribute(cell_mma_kernel, cudaFuncAttributeMaxDynamicSharedMemorySize, cell_smem);

    // 1) init + one-time conversions/swizzles
    zero_state_kernel<<<(3 * B_ * N_ + 511) / 512, 512>>>();
    xconv_kernel<<<(8 << 20) / 256, 256>>>(x);
    wconv_ih_kernel<<<(4 << 20) / 256, 256>>>(Wf_ih, Wb_ih, Wc_ih);
    wswz_bi_kernel<<<(4 << 20) / 256, 256>>>(Wf_hh, Wb_hh);
    wswz_cell_kernel<<<(2 << 20) / 256, 256>>>(Wc_hh);

    // 2) input projections (fp16 mma)
    dim3 ggrid(G_ / 128, (T_ * B_) / 128);
    gemm_f16_kernel<<<ggrid, 256>>>(x16, wih_f, bf, N_, 1, 0);
    gemm_f16_kernel<<<ggrid, 256>>>(x16, wih_b, bb, N_, 1, 1);

    // 3) bilstm recurrence
    bilstm_mma_kernel<<<128, 512, bilstm_smem>>>();

    // 4) cell input projection (K = 2N, A = g_bi16)
    gemm_f16_kernel<<<ggrid, 256>>>(bi16, wih_c, bc, 2 * N_, 0, 2);

    // 5) cell recurrence + output (+ hT/cT tail at final step)
    cell_mma_kernel<<<128, 512, cell_smem>>>(out);
}